// round 1
// baseline (speedup 1.0000x reference)
#include <cuda_runtime.h>
#include <math.h>

#define NSC 7
#define NB 8
#define ADIM 512
#define MAPSZ (NB * ADIM * ADIM)       // 2,097,152 per scale
#define PTS (NSC * MAPSZ)              // 14,680,064 points per coord set

// Scratch (allocation-free; __device__ globals per harness rules)
__device__ float        g_dm[PTS];     // 7 density maps, 56 MB
__device__ float        g_sum[NSC];
__device__ unsigned int g_max[NSC];    // float bits (all values >= 0)
__device__ unsigned int g_cnt;

// ---------------------------------------------------------------------------
// K0: zero scratch (re-zeroed on every call for determinism under graph replay)
// ---------------------------------------------------------------------------
__global__ void k_zero() {
    const int n4 = PTS / 4;
    float4* p = reinterpret_cast<float4*>(g_dm);
    const float4 z = make_float4(0.f, 0.f, 0.f, 0.f);
    for (int j = blockIdx.x * blockDim.x + threadIdx.x; j < n4;
         j += gridDim.x * blockDim.x)
        p[j] = z;
    if (blockIdx.x == 0 && threadIdx.x < NSC) {
        g_sum[threadIdx.x] = 0.f;
        g_max[threadIdx.x] = 0u;
    }
    if (blockIdx.x == 0 && threadIdx.x == 0) g_cnt = 0u;
}

// ---------------------------------------------------------------------------
// K1: bilinear scatter. Each thread handles 4 consecutive points for both
// coordinate sets (r3,c3) and (r4,c4). All 4 points share one (scale,batch)
// map since 4 | 2^18.
// ---------------------------------------------------------------------------
__device__ __forceinline__ void scat1(float* __restrict__ dm, float r, float c) {
    float xf = fminf(fmaxf(floorf(r), 0.f), 511.f);
    float xc = fminf(fmaxf(ceilf(r),  0.f), 511.f);
    float yf = fminf(fmaxf(floorf(c), 0.f), 511.f);
    float yc = fminf(fmaxf(ceilf(c),  0.f), 511.f);
    float xw = r - xf;
    float yw = c - yf;
    int ixf = (int)xf, ixc = (int)xc, iyf = (int)yf, iyc = (int)yc;
    atomicAdd(dm + ixf * ADIM + iyf, (1.f - xw) * (1.f - yw));
    atomicAdd(dm + ixc * ADIM + iyf, xw * (1.f - yw));
    atomicAdd(dm + ixf * ADIM + iyc, (1.f - xw) * yw);
    atomicAdd(dm + ixc * ADIM + iyc, xw * yw);
}

__global__ void k_scatter(const float4* __restrict__ r3, const float4* __restrict__ c3,
                          const float4* __restrict__ r4, const float4* __restrict__ c4) {
    int i = blockIdx.x * blockDim.x + threadIdx.x;   // over PTS/4
    if (i >= PTS / 4) return;
    int idx0 = i * 4;
    float* __restrict__ dm = g_dm + (idx0 & ~(ADIM * ADIM - 1));  // (scale,batch) map base

    float4 rA = r3[i], cA = c3[i];
    float4 rB = r4[i], cB = c4[i];
    scat1(dm, rA.x, cA.x); scat1(dm, rA.y, cA.y);
    scat1(dm, rA.z, cA.z); scat1(dm, rA.w, cA.w);
    scat1(dm, rB.x, cB.x); scat1(dm, rB.y, cB.y);
    scat1(dm, rB.z, cB.z); scat1(dm, rB.w, cB.w);
}

// ---------------------------------------------------------------------------
// K2: per-scale global max (blockIdx.y = scale)
// ---------------------------------------------------------------------------
__global__ void k_max() {
    const int s = blockIdx.y;
    const float4* dm = reinterpret_cast<const float4*>(g_dm + s * MAPSZ);
    const int n4 = MAPSZ / 4;
    float m = 0.f;
    for (int j = blockIdx.x * blockDim.x + threadIdx.x; j < n4;
         j += gridDim.x * blockDim.x) {
        float4 v = dm[j];
        m = fmaxf(m, fmaxf(fmaxf(v.x, v.y), fmaxf(v.z, v.w)));
    }
    #pragma unroll
    for (int o = 16; o; o >>= 1) m = fmaxf(m, __shfl_xor_sync(0xFFFFFFFFu, m, o));
    __shared__ float sm[8];
    int w = threadIdx.x >> 5;
    if ((threadIdx.x & 31) == 0) sm[w] = m;
    __syncthreads();
    if (threadIdx.x == 0) {
        float bm = sm[0];
        for (int k = 1; k < (int)(blockDim.x >> 5); k++) bm = fmaxf(bm, sm[k]);
        atomicMax(&g_max[s], __float_as_uint(bm));  // valid: values >= 0
    }
}

// ---------------------------------------------------------------------------
// K3: masked BCE partial sums per scale (blockIdx.y = scale).
// bce = min(-log(dm/max), 100) at target==1 positions; also count valid once.
// ---------------------------------------------------------------------------
__global__ void k_bce(const float* __restrict__ target) {
    const int s = blockIdx.y;
    const float* __restrict__ dm = g_dm + s * MAPSZ;
    const float maxv = __uint_as_float(g_max[s]);
    float lsum = 0.f;
    unsigned int lcnt = 0;
    const int stride = gridDim.x * blockDim.x;
    for (int j = blockIdx.x * blockDim.x + threadIdx.x; j < MAPSZ; j += stride) {
        float t = __ldg(&target[j]);
        if (t == 1.0f) {
            float p = dm[j] / maxv;               // elementwise div, matches ref
            lsum += fminf(-logf(p), 100.f);       // == -clip(log p, -100)
            lcnt++;
        }
    }
    #pragma unroll
    for (int o = 16; o; o >>= 1) {
        lsum += __shfl_xor_sync(0xFFFFFFFFu, lsum, o);
        lcnt += __shfl_xor_sync(0xFFFFFFFFu, lcnt, o);
    }
    __shared__ float        ssum[8];
    __shared__ unsigned int scnt[8];
    int w = threadIdx.x >> 5;
    if ((threadIdx.x & 31) == 0) { ssum[w] = lsum; scnt[w] = lcnt; }
    __syncthreads();
    if (threadIdx.x == 0) {
        float bs = 0.f; unsigned int bc = 0;
        for (int k = 0; k < (int)(blockDim.x >> 5); k++) { bs += ssum[k]; bc += scnt[k]; }
        atomicAdd(&g_sum[s], bs);
        if (s == 0) atomicAdd(&g_cnt, bc);
    }
}

// ---------------------------------------------------------------------------
// K4: final combine: total = sum_i (sum_i / count), weights all 1.0
// ---------------------------------------------------------------------------
__global__ void k_final(float* __restrict__ out) {
    float c = (float)g_cnt;
    float tot = 0.f;
    #pragma unroll
    for (int i = 0; i < NSC; i++) tot += g_sum[i] / c;
    out[0] = tot;
}

// ---------------------------------------------------------------------------
extern "C" void kernel_launch(void* const* d_in, const int* in_sizes, int n_in,
                              void* d_out, int out_size) {
    const float4* r3 = (const float4*)d_in[0];
    const float4* c3 = (const float4*)d_in[1];
    const float4* r4 = (const float4*)d_in[2];
    const float4* c4 = (const float4*)d_in[3];
    const float*  target = (const float*)d_in[4];
    float* out = (float*)d_out;

    k_zero<<<2048, 256>>>();
    k_scatter<<<(PTS / 4 + 255) / 256, 256>>>(r3, c3, r4, c4);
    k_max<<<dim3(512, NSC), 256>>>();
    k_bce<<<dim3(1024, NSC), 256>>>(target);
    k_final<<<1, 1>>>(out);
}

// round 2
// speedup vs baseline: 1.6833x; 1.6833x over previous
#include <cuda_runtime.h>
#include <math.h>

#define NSC 7
#define NB 8
#define ADIM 512
#define MAPSZ (NB * ADIM * ADIM)       // 2,097,152 per scale
#define PTS (NSC * MAPSZ)              // 14,680,064 points per coord set
#define NMAP (NSC * NB)                // 56 (scale,batch) maps
#define TT 257                         // tiles per dim (padded 514/2)
#define MAPF4 (TT * TT)                // 66049 float4 tiles per map per replica

// Scratch (allocation-free; __device__ globals per harness rules)
// 4 shift-replicas of all 56 maps, stored as 2x2-tiled float4 grids. ~237 MB.
__device__ float4       g_rep[4][NMAP * MAPF4];
__device__ float        g_dm[PTS];     // combined logical maps, 56 MB
__device__ float        g_sum[NSC];
__device__ unsigned int g_max[NSC];    // float bits (values >= 0)
__device__ unsigned int g_cnt;

// ---------------------------------------------------------------------------
// K0: zero scratch (every call: deterministic under graph replay)
// ---------------------------------------------------------------------------
__global__ void k_zero() {
    const int n4 = 4 * NMAP * MAPF4;
    float4* p = &g_rep[0][0];
    const float4 z = make_float4(0.f, 0.f, 0.f, 0.f);
    for (int j = blockIdx.x * blockDim.x + threadIdx.x; j < n4;
         j += gridDim.x * blockDim.x)
        p[j] = z;
    if (blockIdx.x == 0 && threadIdx.x < NSC) {
        g_sum[threadIdx.x] = 0.f;
        g_max[threadIdx.x] = 0u;
    }
    if (blockIdx.x == 0 && threadIdx.x == 0) g_cnt = 0u;
}

// ---------------------------------------------------------------------------
// K1: bilinear scatter — ONE red.global.add.v4.f32 per point.
// Replica (sx,sy) holds logical (x,y) at stored (x+sx, y+sy); choosing
// sx=ixf&1, sy=iyf&1 makes the 2x2 footprint exactly one aligned tile.
// ---------------------------------------------------------------------------
__device__ __forceinline__ void scat1(int m, float r, float c) {
    float xf = fminf(fmaxf(floorf(r), 0.f), 511.f);
    float yf = fminf(fmaxf(floorf(c), 0.f), 511.f);
    float xw = r - xf;
    float yw = c - yf;
    int ix = (int)xf, iy = (int)yf;
    int sx = ix & 1, sy = iy & 1;
    float4* a = &g_rep[sx * 2 + sy][m * MAPF4 + ((ix + sx) >> 1) * TT + ((iy + sy) >> 1)];
    float wx0 = 1.f - xw, wy0 = 1.f - yw;
    // lanes: (dx,dy) = (0,0),(0,1),(1,0),(1,1) -> logical rows ixf/ixf+1, cols iyf/iyf+1
    asm volatile("red.global.add.v4.f32 [%0], {%1, %2, %3, %4};"
                 :: "l"(a), "f"(wx0 * wy0), "f"(wx0 * yw),
                    "f"(xw * wy0), "f"(xw * yw)
                 : "memory");
}

__global__ void k_scatter(const float4* __restrict__ r3, const float4* __restrict__ c3,
                          const float4* __restrict__ r4, const float4* __restrict__ c4) {
    int i = blockIdx.x * blockDim.x + threadIdx.x;   // over PTS/4
    if (i >= PTS / 4) return;
    int m = i >> 16;                                 // (i*4) >> 18: (scale,batch) map id

    float4 rA = r3[i], cA = c3[i];
    float4 rB = r4[i], cB = c4[i];
    scat1(m, rA.x, cA.x); scat1(m, rA.y, cA.y);
    scat1(m, rA.z, cA.z); scat1(m, rA.w, cA.w);
    scat1(m, rB.x, cB.x); scat1(m, rB.y, cB.y);
    scat1(m, rB.z, cB.z); scat1(m, rB.w, cB.w);
}

// ---------------------------------------------------------------------------
// K2: combine 4 replicas -> logical map g_dm, and per-scale max.
// One thread per 2x2 logical block. blockIdx.y = scale.
// ---------------------------------------------------------------------------
__global__ void k_maxcombine() {
    const int s = blockIdx.y;
    int id = blockIdx.x * blockDim.x + threadIdx.x;  // [0, 8*256*256)
    float mx = 0.f;
    if (id < NB * 256 * 256) {
        int b   = id >> 16;
        int rem = id & 65535;
        int bx  = rem >> 8;
        int by  = rem & 255;
        int m   = s * NB + b;

        float acc0 = 0.f, acc1 = 0.f, acc2 = 0.f, acc3 = 0.f; // logical (dx,dy)
        #pragma unroll
        for (int q = 0; q < 4; q++) {
            const int sx = q >> 1, sy = q & 1;
            const float* __restrict__ rm = (const float*)&g_rep[q][m * MAPF4];
            #pragma unroll
            for (int dx = 0; dx < 2; dx++) {
                #pragma unroll
                for (int dy = 0; dy < 2; dy++) {
                    int u = dx + sx, v = dy + sy;     // stored offsets within block
                    int off = ((bx + (u >> 1)) * TT + by + (v >> 1)) * 4
                              + (u & 1) * 2 + (v & 1);
                    float val = rm[off];
                    if (dx == 0) { if (dy == 0) acc0 += val; else acc1 += val; }
                    else         { if (dy == 0) acc2 += val; else acc3 += val; }
                }
            }
        }
        int base = m * (ADIM * ADIM) + (2 * bx) * ADIM + 2 * by;
        *(float2*)(g_dm + base)        = make_float2(acc0, acc1);
        *(float2*)(g_dm + base + ADIM) = make_float2(acc2, acc3);
        mx = fmaxf(fmaxf(acc0, acc1), fmaxf(acc2, acc3));
    }
    #pragma unroll
    for (int o = 16; o; o >>= 1) mx = fmaxf(mx, __shfl_xor_sync(0xFFFFFFFFu, mx, o));
    __shared__ float sm[8];
    int w = threadIdx.x >> 5;
    if ((threadIdx.x & 31) == 0) sm[w] = mx;
    __syncthreads();
    if (threadIdx.x == 0) {
        float bm = sm[0];
        for (int k = 1; k < (int)(blockDim.x >> 5); k++) bm = fmaxf(bm, sm[k]);
        atomicMax(&g_max[s], __float_as_uint(bm));
    }
}

// ---------------------------------------------------------------------------
// K3: masked BCE partial sums per scale (blockIdx.y = scale).
// -log(dm/max) clamped at 100 == min(log(max) - log(dm), 100).
// ---------------------------------------------------------------------------
__global__ void k_bce(const float* __restrict__ target) {
    const int s = blockIdx.y;
    const float* __restrict__ dm = g_dm + s * MAPSZ;
    const float maxv = __uint_as_float(g_max[s]);
    const float lm = logf(maxv);
    float lsum = 0.f;
    unsigned int lcnt = 0;
    const int stride = gridDim.x * blockDim.x;
    for (int j = blockIdx.x * blockDim.x + threadIdx.x; j < MAPSZ; j += stride) {
        float t = __ldg(&target[j]);
        if (t == 1.0f) {
            lsum += fminf(lm - __logf(dm[j]), 100.f);
            lcnt++;
        }
    }
    #pragma unroll
    for (int o = 16; o; o >>= 1) {
        lsum += __shfl_xor_sync(0xFFFFFFFFu, lsum, o);
        lcnt += __shfl_xor_sync(0xFFFFFFFFu, lcnt, o);
    }
    __shared__ float        ssum[8];
    __shared__ unsigned int scnt[8];
    int w = threadIdx.x >> 5;
    if ((threadIdx.x & 31) == 0) { ssum[w] = lsum; scnt[w] = lcnt; }
    __syncthreads();
    if (threadIdx.x == 0) {
        float bs = 0.f; unsigned int bc = 0;
        for (int k = 0; k < (int)(blockDim.x >> 5); k++) { bs += ssum[k]; bc += scnt[k]; }
        atomicAdd(&g_sum[s], bs);
        if (s == 0) atomicAdd(&g_cnt, bc);
    }
}

// ---------------------------------------------------------------------------
// K4: final combine: total = sum_i (sum_i / count), weights all 1.0
// ---------------------------------------------------------------------------
__global__ void k_final(float* __restrict__ out) {
    float c = (float)g_cnt;
    float tot = 0.f;
    #pragma unroll
    for (int i = 0; i < NSC; i++) tot += g_sum[i] / c;
    out[0] = tot;
}

// ---------------------------------------------------------------------------
extern "C" void kernel_launch(void* const* d_in, const int* in_sizes, int n_in,
                              void* d_out, int out_size) {
    const float4* r3 = (const float4*)d_in[0];
    const float4* c3 = (const float4*)d_in[1];
    const float4* r4 = (const float4*)d_in[2];
    const float4* c4 = (const float4*)d_in[3];
    const float*  target = (const float*)d_in[4];
    float* out = (float*)d_out;

    k_zero<<<4096, 256>>>();
    k_scatter<<<(PTS / 4 + 255) / 256, 256>>>(r3, c3, r4, c4);
    k_maxcombine<<<dim3(2048, NSC), 256>>>();
    k_bce<<<dim3(1024, NSC), 256>>>(target);
    k_final<<<1, 1>>>(out);
}

// round 3
// speedup vs baseline: 1.8636x; 1.1071x over previous
#include <cuda_runtime.h>
#include <math.h>

#define NSC 7
#define NB 8
#define ADIM 512
#define MAPSZ (NB * ADIM * ADIM)       // 2,097,152 cells per scale
#define TT 257                         // padded tiles per dim (514/2)
#define MAPF4 (TT * TT)                // 66049 float4 tiles per (map, replica)

// Scratch: 4 shift-replicas per scale, 2x2-tiled float4 grids. ~237 MB.
// Layout scale-major so per-scale zeroing is one contiguous range.
__device__ float4       g_rep[NSC][4][NB * MAPF4];
__device__ float        g_sumlog[NSC];
__device__ unsigned int g_max[NSC];     // float bits (values >= 0)
__device__ unsigned int g_nzero[NSC];
__device__ unsigned int g_npos;

// ---------------------------------------------------------------------------
// K0a: zero the tiny stats
// ---------------------------------------------------------------------------
__global__ void k_zero_stats() {
    if (threadIdx.x < NSC) {
        g_sumlog[threadIdx.x] = 0.f;
        g_max[threadIdx.x] = 0u;
        g_nzero[threadIdx.x] = 0u;
    }
    if (threadIdx.x == 0) g_npos = 0u;
}

// ---------------------------------------------------------------------------
// K0b: zero one scale's replicas (33.8 MB)
// ---------------------------------------------------------------------------
__global__ void k_zero_scale(int s) {
    const int n = 4 * NB * MAPF4;
    float4* p = &g_rep[s][0][0];
    int j = blockIdx.x * blockDim.x + threadIdx.x;
    if (j < n) p[j] = make_float4(0.f, 0.f, 0.f, 0.f);
}

// ---------------------------------------------------------------------------
// K1: bilinear scatter for one scale — ONE red.global.add.v4.f32 per point.
// Replica (sx,sy) holds logical (x,y) at stored (x+sx, y+sy); sx=ixf&1,
// sy=iyf&1 makes the 2x2 footprint exactly one aligned float4 tile.
// ---------------------------------------------------------------------------
__device__ __forceinline__ void scat1(int s, int b, float r, float c) {
    float xf = fminf(fmaxf(floorf(r), 0.f), 511.f);
    float yf = fminf(fmaxf(floorf(c), 0.f), 511.f);
    float xw = r - xf;
    float yw = c - yf;
    int ix = (int)xf, iy = (int)yf;
    int sx = ix & 1, sy = iy & 1;
    float4* a = &g_rep[s][sx * 2 + sy][b * MAPF4 + ((ix + sx) >> 1) * TT + ((iy + sy) >> 1)];
    float wx0 = 1.f - xw, wy0 = 1.f - yw;
    // components: (dx,dy) = (0,0),(0,1),(1,0),(1,1) relative to (ixf,iyf)
    asm volatile("red.global.add.v4.f32 [%0], {%1, %2, %3, %4};"
                 :: "l"(a), "f"(wx0 * wy0), "f"(wx0 * yw),
                    "f"(xw * wy0), "f"(xw * yw)
                 : "memory");
}

__global__ void k_scatter(const float4* __restrict__ r3, const float4* __restrict__ c3,
                          const float4* __restrict__ r4, const float4* __restrict__ c4,
                          int s) {
    int i = blockIdx.x * blockDim.x + threadIdx.x;   // [0, MAPSZ/4)
    if (i >= MAPSZ / 4) return;
    int b = i >> 16;                                 // batch within scale
    const int off = s * (MAPSZ / 4);

    float4 rA = r3[off + i], cA = c3[off + i];
    float4 rB = r4[off + i], cB = c4[off + i];
    scat1(s, b, rA.x, cA.x); scat1(s, b, rA.y, cA.y);
    scat1(s, b, rA.z, cA.z); scat1(s, b, rA.w, cA.w);
    scat1(s, b, rB.x, cB.x); scat1(s, b, rB.y, cB.y);
    scat1(s, b, rB.z, cB.z); scat1(s, b, rB.w, cB.w);
}

// ---------------------------------------------------------------------------
// K2: fused combine + max + masked log-stats for one scale.
// One thread per 2x2 logical block. Combined dm values live in registers only.
// BCE algebra: sum_{mask} min(lm - log(dm), 100)
//            = (npos - nzero)*lm - sum_{mask,dm>0} log(dm) + 100*nzero
// (clamp engages only at dm==0: nonzero dm >= ~1e-40 gives lm-log(dm) << 100)
// ---------------------------------------------------------------------------
__device__ __forceinline__ void stat_cell(float d, float t, float& sl,
                                          unsigned& nz, unsigned& np) {
    if (t == 1.0f) {
        np++;
        if (d == 0.f) nz++;
        else sl += logf(d);
    }
}

__global__ void k_stats(const float* __restrict__ target, int s) {
    int id = blockIdx.x * blockDim.x + threadIdx.x;  // [0, NB*256*256)
    float mx = 0.f, sl = 0.f;
    unsigned nz = 0, np = 0;
    {
        int b   = id >> 16;
        int rem = id & 65535;
        int bx  = rem >> 8;
        int by  = rem & 255;
        int m4  = b * MAPF4;
        int t00 = m4 + bx * TT + by;

        const float4* __restrict__ r00 = &g_rep[s][0][0];  // (sx,sy)=(0,0)
        const float4* __restrict__ r01 = &g_rep[s][1][0];  // (0,1)
        const float4* __restrict__ r10 = &g_rep[s][2][0];  // (1,0)
        const float4* __restrict__ r11 = &g_rep[s][3][0];  // (1,1)

        // logical cells (2bx+dx, 2by+dy), accumulators c[dx][dy]
        float4 A = r00[t00];
        float c00 = A.x, c01 = A.y, c10 = A.z, c11 = A.w;

        float4 B0 = r01[t00], B1 = r01[t00 + 1];
        c00 += B0.y; c10 += B0.w; c01 += B1.x; c11 += B1.z;

        float4 C0 = r10[t00], C1 = r10[t00 + TT];
        c00 += C0.z; c01 += C0.w; c10 += C1.x; c11 += C1.y;

        float4 D00 = r11[t00],     D01 = r11[t00 + 1];
        float4 D10 = r11[t00 + TT], D11 = r11[t00 + TT + 1];
        c00 += D00.w; c01 += D01.z; c10 += D10.y; c11 += D11.x;

        mx = fmaxf(fmaxf(c00, c01), fmaxf(c10, c11));

        const float* tp = target + b * (ADIM * ADIM) + (2 * bx) * ADIM + 2 * by;
        float2 t0 = *(const float2*)tp;
        float2 t1 = *(const float2*)(tp + ADIM);
        stat_cell(c00, t0.x, sl, nz, np);
        stat_cell(c01, t0.y, sl, nz, np);
        stat_cell(c10, t1.x, sl, nz, np);
        stat_cell(c11, t1.y, sl, nz, np);
    }
    #pragma unroll
    for (int o = 16; o; o >>= 1) {
        mx = fmaxf(mx, __shfl_xor_sync(0xFFFFFFFFu, mx, o));
        sl += __shfl_xor_sync(0xFFFFFFFFu, sl, o);
        nz += __shfl_xor_sync(0xFFFFFFFFu, nz, o);
        np += __shfl_xor_sync(0xFFFFFFFFu, np, o);
    }
    __shared__ float    smx[8], ssl[8];
    __shared__ unsigned snz[8], snp[8];
    int w = threadIdx.x >> 5;
    if ((threadIdx.x & 31) == 0) { smx[w] = mx; ssl[w] = sl; snz[w] = nz; snp[w] = np; }
    __syncthreads();
    if (threadIdx.x == 0) {
        float bmx = smx[0], bsl = ssl[0];
        unsigned bnz = snz[0], bnp = snp[0];
        #pragma unroll
        for (int k = 1; k < 8; k++) {
            bmx = fmaxf(bmx, smx[k]); bsl += ssl[k]; bnz += snz[k]; bnp += snp[k];
        }
        atomicMax(&g_max[s], __float_as_uint(bmx));
        atomicAdd(&g_sumlog[s], bsl);
        if (bnz) atomicAdd(&g_nzero[s], bnz);
        if (s == 0) atomicAdd(&g_npos, bnp);
    }
}

// ---------------------------------------------------------------------------
// K3: final: total = sum_s ((npos - nzero_s)*log(max_s) - sumlog_s + 100*nzero_s)/npos
// ---------------------------------------------------------------------------
__global__ void k_final(float* __restrict__ out) {
    float np = (float)g_npos;
    float tot = 0.f;
    #pragma unroll
    for (int i = 0; i < NSC; i++) {
        float lm = logf(__uint_as_float(g_max[i]));
        float nzf = (float)g_nzero[i];
        tot += ((np - nzf) * lm - g_sumlog[i] + 100.f * nzf) / np;
    }
    out[0] = tot;
}

// ---------------------------------------------------------------------------
// Launch: per-scale pipeline across 3 streams (graph fork/join via events).
//   D (capture stream): scatter(0..6), final
//   Z: stats-zero + zero(0..6)    — zero(s+1) overlaps scatter(s)
//   C: stats(0..6)                — stats(s-1) overlaps scatter(s)
// ---------------------------------------------------------------------------
static cudaStream_t sZ = nullptr, sC = nullptr;
static cudaEvent_t  evFork, evZ[NSC], evS[NSC], evZdone, evCdone;

extern "C" void kernel_launch(void* const* d_in, const int* in_sizes, int n_in,
                              void* d_out, int out_size) {
    const float4* r3 = (const float4*)d_in[0];
    const float4* c3 = (const float4*)d_in[1];
    const float4* r4 = (const float4*)d_in[2];
    const float4* c4 = (const float4*)d_in[3];
    const float*  target = (const float*)d_in[4];
    float* out = (float*)d_out;

    if (!sZ) {  // one-time resource creation (host-side only; no device allocs)
        cudaStreamCreateWithFlags(&sZ, cudaStreamNonBlocking);
        cudaStreamCreateWithFlags(&sC, cudaStreamNonBlocking);
        cudaEventCreateWithFlags(&evFork,  cudaEventDisableTiming);
        cudaEventCreateWithFlags(&evZdone, cudaEventDisableTiming);
        cudaEventCreateWithFlags(&evCdone, cudaEventDisableTiming);
        for (int i = 0; i < NSC; i++) {
            cudaEventCreateWithFlags(&evZ[i], cudaEventDisableTiming);
            cudaEventCreateWithFlags(&evS[i], cudaEventDisableTiming);
        }
    }
    cudaStream_t D = 0;

    const int ZBLK = (4 * NB * MAPF4 + 255) / 256;   // 8257
    const int SBLK = (MAPSZ / 4 + 255) / 256;        // 2048
    const int TBLK = (NB * 256 * 256) / 256;         // 2048

    // Fork Z and C off the capture stream
    cudaEventRecord(evFork, D);
    cudaStreamWaitEvent(sZ, evFork, 0);
    cudaStreamWaitEvent(sC, evFork, 0);

    // Z: zero stats, then zero each scale's replicas
    k_zero_stats<<<1, 32, 0, sZ>>>();
    for (int s = 0; s < NSC; s++) {
        k_zero_scale<<<ZBLK, 256, 0, sZ>>>(s);
        cudaEventRecord(evZ[s], sZ);
    }
    cudaEventRecord(evZdone, sZ);

    // D: scatter chain; C: stats chasing it
    for (int s = 0; s < NSC; s++) {
        cudaStreamWaitEvent(D, evZ[s], 0);
        k_scatter<<<SBLK, 256, 0, D>>>(r3, c3, r4, c4, s);
        cudaEventRecord(evS[s], D);
        cudaStreamWaitEvent(sC, evS[s], 0);
        k_stats<<<TBLK, 256, 0, sC>>>(target, s);
    }
    cudaEventRecord(evCdone, sC);

    // Join everything back to D, then final
    cudaStreamWaitEvent(D, evZdone, 0);
    cudaStreamWaitEvent(D, evCdone, 0);
    k_final<<<1, 1, 0, D>>>(out);
}